// round 11
// baseline (speedup 1.0000x reference)
#include <cuda_runtime.h>
#include <cuda_fp16.h>
#include <cstdint>

#define NTHR 256
#define MT 128
#define BSZ 131072
#define NMAT 36
#define TOTAL_SLABS 72       // 36 mats x 2 slabs (K=128 each)
#define SLAB_HALVES 32768
#define SLAB_BYTES 65536
#define STR2 136             // half2 words per act row; 136 mod 32 = 8 -> conflict-free

// smem byte offsets
#define OFF_WBUF 0                      // 2 x 64KB
#define OFF_ACT  131072                 // 128 rows x 136 words x 4B = 69632
#define OFF_BIAS 200704                 // 2 x 256 floats (gc-parity double buffer)
#define OFF_W1S  202752
#define OFF_B1S  203776
#define OFF_W5S  204800
#define OFF_XV   205824                 // 128 x 2 floats
#define OFF_PP   206848                 // 4 x 128 floats
#define OFF_SARR 208896
#define OFF_TARR 209408
#define SMEM_DYN 209920

__device__ __half g_wpack[NMAT * 65536];

// ---------------------------------------------------------------------------
__device__ __forceinline__ void cpasync16(uint32_t dst, const void* src) {
    asm volatile("cp.async.cg.shared.global [%0], [%1], 16;" :: "r"(dst), "l"(src));
}
__device__ __forceinline__ void mma_f16(float acc[4], uint4 a, uint32_t b0, uint32_t b1) {
    asm volatile(
        "mma.sync.aligned.m16n8k16.row.col.f32.f16.f16.f32 "
        "{%0,%1,%2,%3}, {%4,%5,%6,%7}, {%8,%9}, {%0,%1,%2,%3};"
        : "+f"(acc[0]), "+f"(acc[1]), "+f"(acc[2]), "+f"(acc[3])
        : "r"(a.x), "r"(a.y), "r"(a.z), "r"(a.w), "r"(b0), "r"(b1));
}
__device__ __forceinline__ uint32_t h2u(float lo, float hi) {
    __half2 h = __floats2half2_rn(lo, hi);
    return *(uint32_t*)&h;
}

// ---------------------------------------------------------------------------
// prepack: W[k][n] fp32 -> fp16, A-fragment order for m16n8k16 with
// k-permutation kappa (pairs (j, j+8) within each 16-block). Slab = K=128.
// ---------------------------------------------------------------------------
__global__ void prepack_kernel(const float* sW2, const float* sW3, const float* sW4,
                               const float* tW2, const float* tW3, const float* tW4) {
    int idx = blockIdx.x * blockDim.x + threadIdx.x;
    if (idx >= NMAT * 8192) return;
    int lane = idx & 31;
    int mt   = (idx >> 5) & 15;
    int kc   = (idx >> 9) & 7;
    int slab = (idx >> 12) & 1;
    int mat  = idx >> 13;

    int st = mat / 18, rem = mat % 18, l = rem / 3, g = rem % 3;
    const float* src;
    switch (st * 3 + g) {
        case 0: src = sW2; break;
        case 1: src = sW3; break;
        case 2: src = sW4; break;
        case 3: src = tW2; break;
        case 4: src = tW3; break;
        default: src = tW4; break;
    }
    src += l * 65536;

    int v = lane & 3, mlow = lane >> 2;
    int kb = slab * 128 + kc * 16;
    int nb = mt * 16;

    uint4 o;
    o.x = h2u(src[(kb + v)     * 256 + nb + mlow],     src[(kb + v + 8)  * 256 + nb + mlow]);
    o.y = h2u(src[(kb + v)     * 256 + nb + mlow + 8], src[(kb + v + 8)  * 256 + nb + mlow + 8]);
    o.z = h2u(src[(kb + v + 4) * 256 + nb + mlow],     src[(kb + v + 12) * 256 + nb + mlow]);
    o.w = h2u(src[(kb + v + 4) * 256 + nb + mlow + 8], src[(kb + v + 12) * 256 + nb + mlow + 8]);

    *(uint4*)(g_wpack + (size_t)mat * 65536 + slab * SLAB_HALVES
              + ((kc * 16 + mt) * 32 + lane) * 8) = o;
}

// ---------------------------------------------------------------------------
__global__ void __launch_bounds__(NTHR, 1)
realnvp_kernel(const float* __restrict__ X,
               const float* __restrict__ sW1, const float* __restrict__ sB1,
               const float* __restrict__ sB2, const float* __restrict__ sB3,
               const float* __restrict__ sB4, const float* __restrict__ sW5,
               const float* __restrict__ sB5,
               const float* __restrict__ tW1, const float* __restrict__ tB1,
               const float* __restrict__ tB2, const float* __restrict__ tB3,
               const float* __restrict__ tB4, const float* __restrict__ tW5,
               const float* __restrict__ tB5,
               float* __restrict__ out) {
    extern __shared__ char base[];
    uint32_t* actu   = (uint32_t*)(base + OFF_ACT);   // half2 words [row][STR2]
    float*    bias2  = (float*)(base + OFF_BIAS);     // [2][256]
    float*    w1s    = (float*)(base + OFF_W1S);
    float*    b1s    = (float*)(base + OFF_B1S);
    float*    w5s    = (float*)(base + OFF_W5S);
    float*    xv     = (float*)(base + OFF_XV);
    float*    pp     = (float*)(base + OFF_PP);       // [4][128]
    float*    sarr   = (float*)(base + OFF_SARR);
    float*    tarr   = (float*)(base + OFF_TARR);
    uint32_t  wbuf_sh = (uint32_t)__cvta_generic_to_shared(base + OFF_WBUF);

    int tid  = threadIdx.x;
    int wid  = tid >> 5, lane = tid & 31;
    int wm   = wid >> 1;          // 0..3 feature tiles of 64
    int wn   = wid & 1;           // 0..1 sample tiles of 64
    int u    = lane >> 2;         // 0..7
    int v    = lane & 3;          // 0..3
    int gbase = blockIdx.x * MT;

    float ldet = 0.f;
    if (tid < MT) {
        float2 xx = *(const float2*)&X[(gbase + tid) * 2];
        xv[tid * 2 + 0] = logf(xx.x / (1.f - xx.x));
        xv[tid * 2 + 1] = logf(xx.y / (1.f - xx.y));
    }

    // ---- weight slab prefetch (2-buffer ring of 64KB; 256B per thread) ----
    auto prefetch = [&](int q) {
        int qq = (q >= TOTAL_SLABS) ? q - TOTAL_SLABS : q;
        int j = qq >> 1, sl = qq & 1;
        int li = 5 - j / 6;
        int r6 = j % 6;
        int mat = ((r6 / 3) * 6 + li) * 3 + (r6 % 3);
        const __half* src = g_wpack + (size_t)mat * 65536 + sl * SLAB_HALVES + tid * 8;
        uint32_t dst = wbuf_sh + (uint32_t)(q & 1) * SLAB_BYTES + tid * 16;
#pragma unroll
        for (int it = 0; it < 16; it++)
            cpasync16(dst + it * 4096, src + it * 2048);
        asm volatile("cp.async.commit_group;");
    };

    prefetch(0);

    // ---- layer0: thread-pair = one k-pair row (128 rows), 64 samples each ----
    auto layer0 = [&](const float* w1row, const float* b1, int cdim) {
        w1s[tid] = w1row[tid];
        b1s[tid] = b1[tid];
        __syncthreads();
        int r = tid >> 1;                    // 0..127
        int half = tid & 1;
        int k0 = ((r >> 3) << 4) + (r & 7), k1 = k0 + 8;
        float w0 = w1s[k0], bb0 = b1s[k0];
        float w1v = w1s[k1], bb1 = b1s[k1];
        int sbase = half * 64;
#pragma unroll 4
        for (int i = 0; i < 16; i++) {
            uint4 wrds;
            int s = sbase + i * 4;
            float x0 = xv[(s + 0) * 2 + cdim], x1 = xv[(s + 1) * 2 + cdim];
            float x2 = xv[(s + 2) * 2 + cdim], x3 = xv[(s + 3) * 2 + cdim];
            wrds.x = h2u(fmaxf(fmaf(x0, w0, bb0), 0.f), fmaxf(fmaf(x0, w1v, bb1), 0.f));
            wrds.y = h2u(fmaxf(fmaf(x1, w0, bb0), 0.f), fmaxf(fmaf(x1, w1v, bb1), 0.f));
            wrds.z = h2u(fmaxf(fmaf(x2, w0, bb0), 0.f), fmaxf(fmaf(x2, w1v, bb1), 0.f));
            wrds.w = h2u(fmaxf(fmaf(x3, w0, bb0), 0.f), fmaxf(fmaf(x3, w1v, bb1), 0.f));
            *(uint4*)&actu[r * STR2 + s] = wrds;
        }
        // no trailing sync: next gemm's first slab-sync covers act visibility
    };

    // ---- one 128x256 @ 256x256 GEMM (2 K=128 slabs); warp tile m64 x n64 ----
    auto gemm = [&](int gc, const float* biasg, bool fuse,
                    const float* w5col, float b5, bool is_s) {
        float* bias_c = bias2 + (gc & 1) * 256;
        bias_c[tid] = biasg[tid];
        if (fuse) w5s[tid] = w5col[tid * 2];

        float acc[4][8][4];
#pragma unroll
        for (int a = 0; a < 4; a++)
#pragma unroll
            for (int b = 0; b < 8; b++)
#pragma unroll
                for (int q = 0; q < 4; q++) acc[a][b][q] = 0.f;

#pragma unroll 1
        for (int sl = 0; sl < 2; sl++) {
            int q = gc * 2 + sl;
            asm volatile("cp.async.wait_group 0;");
            __syncthreads();             // slab q visible; buf (q+1)&1 free; act ready
            prefetch(q + 1);
            const __half* wb = (const __half*)(base + OFF_WBUF + (q & 1) * SLAB_BYTES);
#pragma unroll
            for (int kc = 0; kc < 8; kc++) {
                uint4 a[4];
#pragma unroll
                for (int mf = 0; mf < 4; mf++)
                    a[mf] = *(const uint4*)(wb + ((kc * 16 + wm * 4 + mf) * 32 + lane) * 8);
                int kg = sl * 8 + kc;
                const uint32_t* p0 = actu + (kg * 8 + v) * STR2 + wn * 64 + u;
                uint32_t b0[8], b1[8];
#pragma unroll
                for (int nf = 0; nf < 8; nf++) {
                    b0[nf] = p0[nf * 8];
                    b1[nf] = p0[4 * STR2 + nf * 8];
                }
#pragma unroll
                for (int mf = 0; mf < 4; mf++)
#pragma unroll
                    for (int nf = 0; nf < 8; nf++)
                        mma_f16(acc[mf][nf], a[mf], b0[nf], b1[nf]);
            }
        }
        __syncthreads();                 // all reads of act done before overwrite

        if (!fuse) {
            // bias + relu + fp16 pair store; row = (wm*4+mf)*8+u holds (f0, f0+8)
#pragma unroll
            for (int mf = 0; mf < 4; mf++) {
                int f0 = wm * 64 + mf * 16 + u;
                int row = (wm * 4 + mf) * 8 + u;
                float bx = bias_c[f0], by = bias_c[f0 + 8];
#pragma unroll
                for (int nf = 0; nf < 8; nf++) {
                    int s0 = wn * 64 + nf * 8 + v * 2;
                    uint2 wr;
                    wr.x = h2u(fmaxf(acc[mf][nf][0] + bx, 0.f),
                               fmaxf(acc[mf][nf][2] + by, 0.f));
                    wr.y = h2u(fmaxf(acc[mf][nf][1] + bx, 0.f),
                               fmaxf(acc[mf][nf][3] + by, 0.f));
                    *(uint2*)&actu[row * STR2 + s0] = wr;
                }
            }
            // no trailing sync (bias double-buffered; act covered by next slab-sync)
        } else {
            // fused H->1 dot
            float p[8][2];
#pragma unroll
            for (int nf = 0; nf < 8; nf++) { p[nf][0] = 0.f; p[nf][1] = 0.f; }
#pragma unroll
            for (int mf = 0; mf < 4; mf++) {
                int f0 = wm * 64 + mf * 16 + u;
                float bx = bias_c[f0], by = bias_c[f0 + 8];
                float wa = w5s[f0],   wb5 = w5s[f0 + 8];
#pragma unroll
                for (int nf = 0; nf < 8; nf++) {
                    float v0 = fmaxf(acc[mf][nf][0] + bx, 0.f);
                    float v1 = fmaxf(acc[mf][nf][1] + bx, 0.f);
                    float v2 = fmaxf(acc[mf][nf][2] + by, 0.f);
                    float v3 = fmaxf(acc[mf][nf][3] + by, 0.f);
                    p[nf][0] = fmaf(v0, wa, fmaf(v2, wb5, p[nf][0]));
                    p[nf][1] = fmaf(v1, wa, fmaf(v3, wb5, p[nf][1]));
                }
            }
#pragma unroll
            for (int nf = 0; nf < 8; nf++) {
#pragma unroll
                for (int j = 0; j < 2; j++) {
                    float t = p[nf][j];
                    t += __shfl_down_sync(0xffffffffu, t, 16);
                    t += __shfl_down_sync(0xffffffffu, t, 8);
                    t += __shfl_down_sync(0xffffffffu, t, 4);
                    if (lane < 4)
                        pp[wm * 128 + wn * 64 + nf * 8 + lane * 2 + j] = t;
                }
            }
            __syncthreads();
            if (tid < MT) {
                float o = pp[tid] + pp[128 + tid] + pp[256 + tid] + pp[384 + tid] + b5;
                if (is_s) sarr[tid] = tanhf(o);
                else      tarr[tid] = o;
            }
        }
    };

    // ---- main flow: 6 coupling layers, reversed ----
    int gc = 0;
    for (int i = 5; i >= 0; i--) {
        int cdim = (i & 1) ? 0 : 1;
        int other = 1 - cdim;

        layer0(sW1 + i * 512 + cdim * 256, sB1 + i * 256, cdim);
        gemm(gc++, sB2 + i * 256, false, 0, 0.f, false);
        gemm(gc++, sB3 + i * 256, false, 0, 0.f, false);
        gemm(gc++, sB4 + i * 256, true, sW5 + i * 512 + other, sB5[i * 2 + other], true);

        layer0(tW1 + i * 512 + cdim * 256, tB1 + i * 256, cdim);
        gemm(gc++, tB2 + i * 256, false, 0, 0.f, false);
        gemm(gc++, tB3 + i * 256, false, 0, 0.f, false);
        gemm(gc++, tB4 + i * 256, true, tW5 + i * 512 + other, tB5[i * 2 + other], false);

        // coupling update (same-tid as sarr/tarr writers; no sync needed)
        if (tid < MT) {
            float sv = sarr[tid], tv = tarr[tid];
            xv[tid * 2 + other] = (xv[tid * 2 + other] - tv) * expf(-sv);
            ldet -= sv;
        }
        __syncthreads();    // xv visible to next layer0 / output
    }

    if (tid < MT) {
        int g = gbase + tid;
        float2 o;
        o.x = 1.f / (1.f + expf(-xv[tid * 2 + 0]));
        o.y = 1.f / (1.f + expf(-xv[tid * 2 + 1]));
        *(float2*)&out[g * 2] = o;
        out[2 * BSZ + g] = ldet;
    }
    asm volatile("cp.async.wait_group 0;");
}

// ---------------------------------------------------------------------------
extern "C" void kernel_launch(void* const* d_in, const int* in_sizes, int n_in,
                              void* d_out, int out_size) {
    const float* X   = (const float*)d_in[0];
    const float* sW1 = (const float*)d_in[1];
    const float* sB1 = (const float*)d_in[2];
    const float* sW2 = (const float*)d_in[3];
    const float* sB2 = (const float*)d_in[4];
    const float* sW3 = (const float*)d_in[5];
    const float* sB3 = (const float*)d_in[6];
    const float* sW4 = (const float*)d_in[7];
    const float* sB4 = (const float*)d_in[8];
    const float* sW5 = (const float*)d_in[9];
    const float* sB5 = (const float*)d_in[10];
    const float* tW1 = (const float*)d_in[11];
    const float* tB1 = (const float*)d_in[12];
    const float* tW2 = (const float*)d_in[13];
    const float* tB2 = (const float*)d_in[14];
    const float* tW3 = (const float*)d_in[15];
    const float* tB3 = (const float*)d_in[16];
    const float* tW4 = (const float*)d_in[17];
    const float* tB4 = (const float*)d_in[18];
    const float* tW5 = (const float*)d_in[19];
    const float* tB5 = (const float*)d_in[20];

    cudaFuncSetAttribute(realnvp_kernel, cudaFuncAttributeMaxDynamicSharedMemorySize,
                         SMEM_DYN);

    prepack_kernel<<<(NMAT * 8192 + 255) / 256, 256>>>(sW2, sW3, sW4, tW2, tW3, tW4);
    realnvp_kernel<<<BSZ / MT, NTHR, SMEM_DYN>>>(
        X, sW1, sB1, sB2, sB3, sB4, sW5, sB5,
        tW1, tB1, tB2, tB3, tB4, tW5, tB5, (float*)d_out);
}

// round 12
// speedup vs baseline: 1.0270x; 1.0270x over previous
#include <cuda_runtime.h>
#include <cuda_fp16.h>
#include <cstdint>

#define NTHR 128
#define MT 64
#define BSZ 131072
#define NMAT 36
#define TOTAL_SLABS 144      // 36 mats x 4 slabs (K=64 each)
#define SLAB_HALVES 16384
#define SLAB_BYTES 32768
#define STR2 72              // half2 words per act row; 72 mod 32 = 8 -> conflict-free

// smem byte offsets
#define OFF_WBUF 0                      // 2 x 32KB
#define OFF_ACT  65536                  // 128 rows x 72 words x 4B = 36864
#define OFF_BIAS 102400                 // 2 x 256 floats (gc-parity double buffer)
#define OFF_W1S  104448
#define OFF_B1S  105472
#define OFF_W5S  106496
#define OFF_XV   107520                 // 64 x 2 floats
#define OFF_PP   108032                 // 4 x 64 floats
#define OFF_SARR 109056
#define OFF_TARR 109312
#define SMEM_DYN 109568

__device__ __half g_wpack[NMAT * 65536];

// ---------------------------------------------------------------------------
__device__ __forceinline__ void cpasync16(uint32_t dst, const void* src) {
    asm volatile("cp.async.cg.shared.global [%0], [%1], 16;" :: "r"(dst), "l"(src));
}
__device__ __forceinline__ void mma_f16(float acc[4], uint4 a, uint32_t b0, uint32_t b1) {
    asm volatile(
        "mma.sync.aligned.m16n8k16.row.col.f32.f16.f16.f32 "
        "{%0,%1,%2,%3}, {%4,%5,%6,%7}, {%8,%9}, {%0,%1,%2,%3};"
        : "+f"(acc[0]), "+f"(acc[1]), "+f"(acc[2]), "+f"(acc[3])
        : "r"(a.x), "r"(a.y), "r"(a.z), "r"(a.w), "r"(b0), "r"(b1));
}
__device__ __forceinline__ uint32_t h2u(float lo, float hi) {
    __half2 h = __floats2half2_rn(lo, hi);
    return *(uint32_t*)&h;
}

// ---------------------------------------------------------------------------
// prepack: W[k][n] fp32 -> fp16, A-fragment order for m16n8k16 with
// k-permutation kappa (pairs (j, j+8) within each 16-block). Slab = K=64.
// ---------------------------------------------------------------------------
__global__ void prepack_kernel(const float* sW2, const float* sW3, const float* sW4,
                               const float* tW2, const float* tW3, const float* tW4) {
    int idx = blockIdx.x * blockDim.x + threadIdx.x;
    if (idx >= NMAT * 8192) return;
    int lane = idx & 31;
    int mt   = (idx >> 5) & 15;
    int kc   = (idx >> 9) & 3;
    int slab = (idx >> 11) & 3;
    int mat  = idx >> 13;

    int st = mat / 18, rem = mat % 18, l = rem / 3, g = rem % 3;
    const float* src;
    switch (st * 3 + g) {
        case 0: src = sW2; break;
        case 1: src = sW3; break;
        case 2: src = sW4; break;
        case 3: src = tW2; break;
        case 4: src = tW3; break;
        default: src = tW4; break;
    }
    src += l * 65536;

    int v = lane & 3, mlow = lane >> 2;
    int kb = slab * 64 + kc * 16;
    int nb = mt * 16;

    uint4 o;
    o.x = h2u(src[(kb + v)     * 256 + nb + mlow],     src[(kb + v + 8)  * 256 + nb + mlow]);
    o.y = h2u(src[(kb + v)     * 256 + nb + mlow + 8], src[(kb + v + 8)  * 256 + nb + mlow + 8]);
    o.z = h2u(src[(kb + v + 4) * 256 + nb + mlow],     src[(kb + v + 12) * 256 + nb + mlow]);
    o.w = h2u(src[(kb + v + 4) * 256 + nb + mlow + 8], src[(kb + v + 12) * 256 + nb + mlow + 8]);

    *(uint4*)(g_wpack + (size_t)mat * 65536 + slab * SLAB_HALVES
              + ((kc * 16 + mt) * 32 + lane) * 8) = o;
}

// ---------------------------------------------------------------------------
__global__ void __launch_bounds__(NTHR, 2)
realnvp_kernel(const float* __restrict__ X,
               const float* __restrict__ sW1, const float* __restrict__ sB1,
               const float* __restrict__ sB2, const float* __restrict__ sB3,
               const float* __restrict__ sB4, const float* __restrict__ sW5,
               const float* __restrict__ sB5,
               const float* __restrict__ tW1, const float* __restrict__ tB1,
               const float* __restrict__ tB2, const float* __restrict__ tB3,
               const float* __restrict__ tB4, const float* __restrict__ tW5,
               const float* __restrict__ tB5,
               float* __restrict__ out) {
    extern __shared__ char base[];
    uint32_t* actu   = (uint32_t*)(base + OFF_ACT);   // half2 words [row][STR2]
    float*    bias2  = (float*)(base + OFF_BIAS);     // [2][256]
    float*    w1s    = (float*)(base + OFF_W1S);
    float*    b1s    = (float*)(base + OFF_B1S);
    float*    w5s    = (float*)(base + OFF_W5S);
    float*    xv     = (float*)(base + OFF_XV);
    float*    pp     = (float*)(base + OFF_PP);       // [4][64]
    float*    sarr   = (float*)(base + OFF_SARR);
    float*    tarr   = (float*)(base + OFF_TARR);
    uint32_t  wbuf_sh = (uint32_t)__cvta_generic_to_shared(base + OFF_WBUF);

    int tid  = threadIdx.x;
    int wid  = tid >> 5, lane = tid & 31;     // wid = feature tile of 64 (0..3)
    int u    = lane >> 2;                     // 0..7
    int v    = lane & 3;                      // 0..3
    int gbase = blockIdx.x * MT;

    // hoisted loop-invariant bases
    const uint32_t* actu_b = actu + v * STR2 + u;          // B-frag base
    const int a_off = (wid * 4) * 32 * 8 + lane * 8;       // A-frag byte/2 offset base

    float ldet = 0.f;
    if (tid < MT) {
        float2 xx = *(const float2*)&X[(gbase + tid) * 2];
        xv[tid * 2 + 0] = logf(xx.x / (1.f - xx.x));
        xv[tid * 2 + 1] = logf(xx.y / (1.f - xx.y));
    }

    // ---- weight slab prefetch (2-buffer ring of 32KB; 256B per thread) ----
    auto prefetch = [&](int q) {
        int qq = (q >= TOTAL_SLABS) ? q - TOTAL_SLABS : q;
        int j = qq >> 2, sl = qq & 3;
        int li = 5 - j / 6;
        int r6 = j % 6;
        int mat = ((r6 / 3) * 6 + li) * 3 + (r6 % 3);
        const __half* src = g_wpack + (size_t)mat * 65536 + sl * SLAB_HALVES + tid * 8;
        uint32_t dst = wbuf_sh + (uint32_t)(q & 1) * SLAB_BYTES + tid * 16;
#pragma unroll
        for (int it = 0; it < 16; it++)
            cpasync16(dst + it * 2048, src + it * 1024);
        asm volatile("cp.async.commit_group;");
    };

    prefetch(0);

    // ---- layer0: thread = one k-pair row (128 rows), 64 samples each ----
    auto layer0 = [&](const float* w1row, const float* b1, int cdim) {
        w1s[tid] = w1row[tid]; w1s[tid + 128] = w1row[tid + 128];
        b1s[tid] = b1[tid];    b1s[tid + 128] = b1[tid + 128];
        __syncthreads();
        int r = tid;
        int k0 = ((r >> 3) << 4) + (r & 7), k1 = k0 + 8;
        float w0 = w1s[k0], bb0 = b1s[k0];
        float w1v = w1s[k1], bb1 = b1s[k1];
#pragma unroll 4
        for (int i = 0; i < 16; i++) {
            uint4 wrds;
            int s = i * 4;
            float x0 = xv[(s + 0) * 2 + cdim], x1 = xv[(s + 1) * 2 + cdim];
            float x2 = xv[(s + 2) * 2 + cdim], x3 = xv[(s + 3) * 2 + cdim];
            wrds.x = h2u(fmaxf(fmaf(x0, w0, bb0), 0.f), fmaxf(fmaf(x0, w1v, bb1), 0.f));
            wrds.y = h2u(fmaxf(fmaf(x1, w0, bb0), 0.f), fmaxf(fmaf(x1, w1v, bb1), 0.f));
            wrds.z = h2u(fmaxf(fmaf(x2, w0, bb0), 0.f), fmaxf(fmaf(x2, w1v, bb1), 0.f));
            wrds.w = h2u(fmaxf(fmaf(x3, w0, bb0), 0.f), fmaxf(fmaf(x3, w1v, bb1), 0.f));
            *(uint4*)&actu[r * STR2 + s] = wrds;
        }
        // no trailing sync: next gemm's first slab-sync covers act visibility
    };

    // ---- one 64x256 @ 256x256 GEMM; reg ping-pong on A and B fragments ----
    auto gemm = [&](int gc, const float* biasg, bool fuse,
                    const float* w5col, float b5, bool is_s) {
        float* bias_c = bias2 + (gc & 1) * 256;
        bias_c[tid] = biasg[tid];
        bias_c[tid + 128] = biasg[tid + 128];
        if (fuse) { w5s[tid] = w5col[tid * 2]; w5s[tid + 128] = w5col[(tid + 128) * 2]; }

        float acc[4][8][4];
#pragma unroll
        for (int a = 0; a < 4; a++)
#pragma unroll
            for (int b = 0; b < 8; b++)
#pragma unroll
                for (int q = 0; q < 4; q++) acc[a][b][q] = 0.f;

        uint4    af[2][4];
        uint32_t bf[2][16];

        // B-frag loader: act is stable for the whole GEMM -> no guard needed
        auto loadB = [&](uint32_t* b, int kg) {
            const uint32_t* p0 = actu_b + kg * 8 * STR2;
#pragma unroll
            for (int nf = 0; nf < 8; nf++) {
                b[nf]     = p0[nf * 8];
                b[8 + nf] = p0[4 * STR2 + nf * 8];
            }
        };

        loadB(bf[0], 0);            // kg = 0 preload

#pragma unroll 1
        for (int sl = 0; sl < 4; sl++) {
            int q = gc * 4 + sl;
            asm volatile("cp.async.wait_group 0;");
            __syncthreads();         // slab q visible; buf (q+1)&1 free; act ready
            prefetch(q + 1);
            const __half* wb = (const __half*)(base + OFF_WBUF + (q & 1) * SLAB_BYTES);
            // A-frags for kc=0 of this slab (gated by the sync above)
#pragma unroll
            for (int mf = 0; mf < 4; mf++)
                af[0][mf] = *(const uint4*)(wb + a_off + (mf * 32) * 8);
#pragma unroll
            for (int kc = 0; kc < 4; kc++) {
                int p = kc & 1, np = p ^ 1;
                if (kc < 3) {
                    // prefetch next step's A (same slab) and B
#pragma unroll
                    for (int mf = 0; mf < 4; mf++)
                        af[np][mf] = *(const uint4*)(wb + a_off + ((kc + 1) * 16 * 32 + mf * 32) * 8);
                    loadB(bf[np], sl * 4 + kc + 1);
                } else {
                    // next slab's first B (act-sourced; crosses boundary safely)
                    loadB(bf[np], (sl * 4 + kc + 1) & 15);
                }
#pragma unroll
                for (int mf = 0; mf < 4; mf++)
#pragma unroll
                    for (int nf = 0; nf < 8; nf++)
                        mma_f16(acc[mf][nf], af[p][mf], bf[p][nf], bf[p][8 + nf]);
            }
        }
        __syncthreads();                 // all reads of act done before overwrite

        if (!fuse) {
            // bias + relu + fp16 pair store; row = (wid*4+mf)*8+u holds (f0, f0+8)
#pragma unroll
            for (int mf = 0; mf < 4; mf++) {
                int f0 = wid * 64 + mf * 16 + u;
                int row = (wid * 4 + mf) * 8 + u;
                float bx = bias_c[f0], by = bias_c[f0 + 8];
#pragma unroll
                for (int nf = 0; nf < 8; nf++) {
                    int s0 = nf * 8 + v * 2;
                    uint2 wr;
                    wr.x = h2u(fmaxf(acc[mf][nf][0] + bx, 0.f),
                               fmaxf(acc[mf][nf][2] + by, 0.f));
                    wr.y = h2u(fmaxf(acc[mf][nf][1] + bx, 0.f),
                               fmaxf(acc[mf][nf][3] + by, 0.f));
                    *(uint2*)&actu[row * STR2 + s0] = wr;
                }
            }
            // no trailing sync (bias double-buffered; act covered by next slab-sync)
        } else {
            // fused H->1 dot
            float p[8][2];
#pragma unroll
            for (int nf = 0; nf < 8; nf++) { p[nf][0] = 0.f; p[nf][1] = 0.f; }
#pragma unroll
            for (int mf = 0; mf < 4; mf++) {
                int f0 = wid * 64 + mf * 16 + u;
                float bx = bias_c[f0], by = bias_c[f0 + 8];
                float wa = w5s[f0],   wb5 = w5s[f0 + 8];
#pragma unroll
                for (int nf = 0; nf < 8; nf++) {
                    float v0 = fmaxf(acc[mf][nf][0] + bx, 0.f);
                    float v1 = fmaxf(acc[mf][nf][1] + bx, 0.f);
                    float v2 = fmaxf(acc[mf][nf][2] + by, 0.f);
                    float v3 = fmaxf(acc[mf][nf][3] + by, 0.f);
                    p[nf][0] = fmaf(v0, wa, fmaf(v2, wb5, p[nf][0]));
                    p[nf][1] = fmaf(v1, wa, fmaf(v3, wb5, p[nf][1]));
                }
            }
#pragma unroll
            for (int nf = 0; nf < 8; nf++) {
#pragma unroll
                for (int j = 0; j < 2; j++) {
                    float t = p[nf][j];
                    t += __shfl_down_sync(0xffffffffu, t, 16);
                    t += __shfl_down_sync(0xffffffffu, t, 8);
                    t += __shfl_down_sync(0xffffffffu, t, 4);
                    if (lane < 4)
                        pp[wid * 64 + nf * 8 + lane * 2 + j] = t;
                }
            }
            __syncthreads();
            if (tid < MT) {
                float o = pp[tid] + pp[64 + tid] + pp[128 + tid] + pp[192 + tid] + b5;
                if (is_s) sarr[tid] = tanhf(o);
                else      tarr[tid] = o;
            }
        }
    };

    // ---- main flow: 6 coupling layers, reversed ----
    int gc = 0;
    for (int i = 5; i >= 0; i--) {
        int cdim = (i & 1) ? 0 : 1;
        int other = 1 - cdim;

        layer0(sW1 + i * 512 + cdim * 256, sB1 + i * 256, cdim);
        gemm(gc++, sB2 + i * 256, false, 0, 0.f, false);
        gemm(gc++, sB3 + i * 256, false, 0, 0.f, false);
        gemm(gc++, sB4 + i * 256, true, sW5 + i * 512 + other, sB5[i * 2 + other], true);

        layer0(tW1 + i * 512 + cdim * 256, tB1 + i * 256, cdim);
        gemm(gc++, tB2 + i * 256, false, 0, 0.f, false);
        gemm(gc++, tB3 + i * 256, false, 0, 0.f, false);
        gemm(gc++, tB4 + i * 256, true, tW5 + i * 512 + other, tB5[i * 2 + other], false);

        // coupling update (same-tid as sarr/tarr writers; no sync needed)
        if (tid < MT) {
            float sv = sarr[tid], tv = tarr[tid];
            xv[tid * 2 + other] = (xv[tid * 2 + other] - tv) * expf(-sv);
            ldet -= sv;
        }
        __syncthreads();    // xv visible to next layer0 / output
    }

    if (tid < MT) {
        int g = gbase + tid;
        float2 o;
        o.x = 1.f / (1.f + expf(-xv[tid * 2 + 0]));
        o.y = 1.f / (1.f + expf(-xv[tid * 2 + 1]));
        *(float2*)&out[g * 2] = o;
        out[2 * BSZ + g] = ldet;
    }
    asm volatile("cp.async.wait_group 0;");
}

// ---------------------------------------------------------------------------
extern "C" void kernel_launch(void* const* d_in, const int* in_sizes, int n_in,
                              void* d_out, int out_size) {
    const float* X   = (const float*)d_in[0];
    const float* sW1 = (const float*)d_in[1];
    const float* sB1 = (const float*)d_in[2];
    const float* sW2 = (const float*)d_in[3];
    const float* sB2 = (const float*)d_in[4];
    const float* sW3 = (const float*)d_in[5];
    const float* sB3 = (const float*)d_in[6];
    const float* sW4 = (const float*)d_in[7];
    const float* sB4 = (const float*)d_in[8];
    const float* sW5 = (const float*)d_in[9];
    const float* sB5 = (const float*)d_in[10];
    const float* tW1 = (const float*)d_in[11];
    const float* tB1 = (const float*)d_in[12];
    const float* tW2 = (const float*)d_in[13];
    const float* tB2 = (const float*)d_in[14];
    const float* tW3 = (const float*)d_in[15];
    const float* tB3 = (const float*)d_in[16];
    const float* tW4 = (const float*)d_in[17];
    const float* tB4 = (const float*)d_in[18];
    const float* tW5 = (const float*)d_in[19];
    const float* tB5 = (const float*)d_in[20];

    cudaFuncSetAttribute(realnvp_kernel, cudaFuncAttributeMaxDynamicSharedMemorySize,
                         SMEM_DYN);

    prepack_kernel<<<(NMAT * 8192 + 255) / 256, 256>>>(sW2, sW3, sW4, tW2, tW3, tW4);
    realnvp_kernel<<<BSZ / MT, NTHR, SMEM_DYN>>>(
        X, sW1, sB1, sB2, sB3, sB4, sW5, sB5,
        tW1, tB1, tB2, tB3, tB4, tW5, tB5, (float*)d_out);
}